// round 4
// baseline (speedup 1.0000x reference)
#include <cuda_runtime.h>
#include <cstdint>

#define N_NODES 100000
#define N_EDGES 3200000
#define F 128
#define HQ 256
#define ADIM 10

// Scratch (static __device__ arrays: allocation-free per harness rules)
__device__ __align__(16) float g_xw[(size_t)N_NODES * F];   // relu(x@We+be)@Wg
__device__ __align__(16) float g_agg[(size_t)N_NODES * F];  // scatter accumulator
__device__ float g_dinv[N_NODES];                           // deg -> rsqrt(deg)
__device__ int   g_is64;                                    // edge_index dtype flag

// ---- packed f32x2 helpers (Blackwell FFMA2 path) ----
static __device__ __forceinline__ unsigned long long pack2(float lo, float hi) {
    unsigned long long r;
    asm("mov.b64 %0, {%1, %2};" : "=l"(r) : "f"(lo), "f"(hi));
    return r;
}
static __device__ __forceinline__ void fma2(unsigned long long& d,
                                            unsigned long long a,
                                            unsigned long long b) {
    asm("fma.rn.f32x2 %0, %1, %2, %0;" : "+l"(d) : "l"(a), "l"(b));
}
static __device__ __forceinline__ float2 unpack2(unsigned long long v) {
    float2 f;
    asm("mov.b64 {%0, %1}, %2;" : "=f"(f.x), "=f"(f.y) : "l"(v));
    return f;
}

// ---- edge-index dtype detection ----
// If dtype is int64 (little-endian), high words of the first 32 values are all 0
// (indices < 100000). If int32, odd words are random indices; P(all 32 == 0) ~ 1e-160.
__global__ void k_detect(const int* __restrict__ ei) {
    int v = ei[2 * threadIdx.x + 1];
    unsigned m = __ballot_sync(0xffffffffu, v != 0);
    if (threadIdx.x == 0) g_is64 = (m == 0) ? 1 : 0;
}

static __device__ __forceinline__ int eidx(const void* ei, int is64, long long pos) {
    return is64 ? (int)((const long long*)ei)[pos] : ((const int*)ei)[pos];
}

// ---- init: zero agg, deg = 1 (self-loop) ----
__global__ void k_init() {
    int stride = gridDim.x * blockDim.x;
    int i = blockIdx.x * blockDim.x + threadIdx.x;
    float4 z = make_float4(0.f, 0.f, 0.f, 0.f);
    float4* agg4 = reinterpret_cast<float4*>(g_agg);
    const int n4 = N_NODES * F / 4;
    for (int j = i; j < n4; j += stride) agg4[j] = z;
    for (int j = i; j < N_NODES; j += stride) g_dinv[j] = 1.0f;
}

// ---- in-degree count (fp32 add of small ints: exact) ----
__global__ void k_degree(const void* __restrict__ ei) {
    int is64 = g_is64;
    int e = blockIdx.x * blockDim.x + threadIdx.x;
    if (e < N_EDGES)
        atomicAdd(&g_dinv[eidx(ei, is64, (long long)N_EDGES + e)], 1.0f);
}

__global__ void k_rsqrt() {
    int i = blockIdx.x * blockDim.x + threadIdx.x;
    if (i < N_NODES) g_dinv[i] = rsqrtf(g_dinv[i]);
}

// ==================== fused1: xw = relu(x@We + be) @ Wg ====================
// M=128 rows/block, 256 threads, 8x8 register tiles, transposed act tiles in smem.
#define XT_S 132  // padded row stride for transposed tiles (float4-aligned)

__global__ void __launch_bounds__(256, 1)
k_fused1(const float* __restrict__ x, const float* __restrict__ We,
         const float* __restrict__ be, const float* __restrict__ Wg) {
    extern __shared__ float smem[];
    float* sW  = smem;                    // 128*128
    float* sXT = smem + 16384;            // 128 * XT_S  (sXT[k*XT_S + r])
    float* sHT = sXT + 128 * XT_S;        // 128 * XT_S
    float* sBe = sHT + 128 * XT_S;        // 128

    const int tid = threadIdx.x;
    const int base = blockIdx.x * 128;

    for (int idx = tid; idx < 16384; idx += 256) sW[idx] = We[idx];
    if (tid < 128) sBe[tid] = be[tid];
    for (int idx = tid; idx < 128 * F; idx += 256) {
        int r = idx >> 7, c = idx & 127;
        int node = base + r;
        sXT[c * XT_S + r] = (node < N_NODES) ? x[(size_t)node * F + c] : 0.f;
    }
    __syncthreads();

    const int tr = tid & 15, tc = tid >> 4;
    const int r0 = tr * 8, c0 = tc * 8;

    unsigned long long acc[8][4];
    #pragma unroll
    for (int ri = 0; ri < 8; ri++)
        #pragma unroll
        for (int cj = 0; cj < 4; cj++)
            acc[ri][cj] = pack2(sBe[c0 + 2 * cj], sBe[c0 + 2 * cj + 1]);

    // stage 1: h = relu(x@We + be)
    #pragma unroll 4
    for (int k = 0; k < F; k++) {
        float4 a0 = *(const float4*)&sXT[k * XT_S + r0];
        float4 a1 = *(const float4*)&sXT[k * XT_S + r0 + 4];
        float4 w0 = *(const float4*)&sW[k * F + c0];
        float4 w1 = *(const float4*)&sW[k * F + c0 + 4];
        unsigned long long w[4] = { pack2(w0.x, w0.y), pack2(w0.z, w0.w),
                                    pack2(w1.x, w1.y), pack2(w1.z, w1.w) };
        float a[8] = {a0.x, a0.y, a0.z, a0.w, a1.x, a1.y, a1.z, a1.w};
        #pragma unroll
        for (int ri = 0; ri < 8; ri++) {
            unsigned long long av = pack2(a[ri], a[ri]);
            #pragma unroll
            for (int cj = 0; cj < 4; cj++) fma2(acc[ri][cj], av, w[cj]);
        }
    }

    // relu + transposed store of h into sHT
    #pragma unroll
    for (int cj = 0; cj < 4; cj++) {
        float2 v[8];
        #pragma unroll
        for (int ri = 0; ri < 8; ri++) v[ri] = unpack2(acc[ri][cj]);
        int c = c0 + 2 * cj;
        *(float4*)&sHT[c * XT_S + r0] =
            make_float4(fmaxf(v[0].x, 0.f), fmaxf(v[1].x, 0.f),
                        fmaxf(v[2].x, 0.f), fmaxf(v[3].x, 0.f));
        *(float4*)&sHT[c * XT_S + r0 + 4] =
            make_float4(fmaxf(v[4].x, 0.f), fmaxf(v[5].x, 0.f),
                        fmaxf(v[6].x, 0.f), fmaxf(v[7].x, 0.f));
        *(float4*)&sHT[(c + 1) * XT_S + r0] =
            make_float4(fmaxf(v[0].y, 0.f), fmaxf(v[1].y, 0.f),
                        fmaxf(v[2].y, 0.f), fmaxf(v[3].y, 0.f));
        *(float4*)&sHT[(c + 1) * XT_S + r0 + 4] =
            make_float4(fmaxf(v[4].y, 0.f), fmaxf(v[5].y, 0.f),
                        fmaxf(v[6].y, 0.f), fmaxf(v[7].y, 0.f));
    }
    __syncthreads();
    for (int idx = tid; idx < 16384; idx += 256) sW[idx] = Wg[idx];
    __syncthreads();

    // stage 2: xw = h @ Wg
    #pragma unroll
    for (int ri = 0; ri < 8; ri++)
        #pragma unroll
        for (int cj = 0; cj < 4; cj++) acc[ri][cj] = 0ULL;

    #pragma unroll 4
    for (int k = 0; k < F; k++) {
        float4 a0 = *(const float4*)&sHT[k * XT_S + r0];
        float4 a1 = *(const float4*)&sHT[k * XT_S + r0 + 4];
        float4 w0 = *(const float4*)&sW[k * F + c0];
        float4 w1 = *(const float4*)&sW[k * F + c0 + 4];
        unsigned long long w[4] = { pack2(w0.x, w0.y), pack2(w0.z, w0.w),
                                    pack2(w1.x, w1.y), pack2(w1.z, w1.w) };
        float a[8] = {a0.x, a0.y, a0.z, a0.w, a1.x, a1.y, a1.z, a1.w};
        #pragma unroll
        for (int ri = 0; ri < 8; ri++) {
            unsigned long long av = pack2(a[ri], a[ri]);
            #pragma unroll
            for (int cj = 0; cj < 4; cj++) fma2(acc[ri][cj], av, w[cj]);
        }
    }

    #pragma unroll
    for (int ri = 0; ri < 8; ri++) {
        int node = base + r0 + ri;
        if (node < N_NODES) {
            float* dst = &g_xw[(size_t)node * F + c0];
            *(ulonglong2*)(dst)     = make_ulonglong2(acc[ri][0], acc[ri][1]);
            *(ulonglong2*)(dst + 4) = make_ulonglong2(acc[ri][2], acc[ri][3]);
        }
    }
}

// ==================== edge scatter: warp/edge, red.add.v4 ====================
__global__ void k_scatter(const void* __restrict__ ei) {
    int is64 = g_is64;
    int warp = (blockIdx.x * blockDim.x + threadIdx.x) >> 5;
    int lane = threadIdx.x & 31;
    long long e0 = (long long)warp * 4;
    #pragma unroll
    for (int i = 0; i < 4; i++) {
        long long e = e0 + i;
        if (e >= N_EDGES) return;
        int s = eidx(ei, is64, e);
        int d = eidx(ei, is64, (long long)N_EDGES + e);
        float coef = g_dinv[s] * g_dinv[d];
        float4 v = *reinterpret_cast<const float4*>(&g_xw[(size_t)s * F + lane * 4]);
        float4 m = make_float4(v.x * coef, v.y * coef, v.z * coef, v.w * coef);
        float* p = &g_agg[(size_t)d * F + lane * 4];
        asm volatile("red.global.add.v4.f32 [%0], {%1, %2, %3, %4};"
                     :: "l"(p), "f"(m.x), "f"(m.y), "f"(m.z), "f"(m.w)
                     : "memory");
    }
}

// ==================== fused2: h2 -> relu(h2@W1+b1)@W2+b2 ====================
// M=64 rows/block, 256 threads, 8x8 tiles.
#define HT_S 68  // padded stride for 64-row transposed tile

__global__ void __launch_bounds__(256, 1)
k_fused2(const float* __restrict__ bg, const float* __restrict__ W1,
         const float* __restrict__ b1, const float* __restrict__ W2,
         const float* __restrict__ b2, float* __restrict__ out) {
    extern __shared__ float smem[];
    float* sW1  = smem;                   // 128*256 = 32768
    float* sHT  = sW1 + 32768;            // 128 * HT_S = 8704
    float* sW2  = sHT + 128 * HT_S;       // 2560
    float* sB1  = sW2 + 2560;             // 256
    float* sB2  = sB1 + 256;              // 16
    float* sOut = sB2 + 16;               // 8 warps * 640 = 5120

    const int tid = threadIdx.x;
    const int base = blockIdx.x * 64;

    for (int idx = tid; idx < 32768; idx += 256) sW1[idx] = W1[idx];
    for (int idx = tid; idx < 2560; idx += 256) sW2[idx] = W2[idx];
    sB1[tid] = b1[tid];
    if (tid < ADIM) sB2[tid] = b2[tid];

    // h2 = relu(agg + xw*dinv^2 + bg), stored transposed
    for (int idx = tid; idx < 64 * F; idx += 256) {
        int r = idx >> 7, c = idx & 127;
        int node = base + r;
        float v = 0.f;
        if (node < N_NODES) {
            float di = g_dinv[node];
            v = fmaxf(g_agg[(size_t)node * F + c] +
                      g_xw[(size_t)node * F + c] * di * di + bg[c], 0.f);
        }
        sHT[c * HT_S + r] = v;
    }
    __syncthreads();

    const int tr = tid & 7, tc = tid >> 3;
    const int r0 = tr * 8, c0 = tc * 8;
    const int lane = tid & 31, wrp = tid >> 5;

    unsigned long long acc[8][4];
    #pragma unroll
    for (int ri = 0; ri < 8; ri++)
        #pragma unroll
        for (int cj = 0; cj < 4; cj++)
            acc[ri][cj] = pack2(sB1[c0 + 2 * cj], sB1[c0 + 2 * cj + 1]);

    #pragma unroll 4
    for (int k = 0; k < F; k++) {
        float4 a0 = *(const float4*)&sHT[k * HT_S + r0];
        float4 a1 = *(const float4*)&sHT[k * HT_S + r0 + 4];
        float4 w0 = *(const float4*)&sW1[k * HQ + c0];
        float4 w1 = *(const float4*)&sW1[k * HQ + c0 + 4];
        unsigned long long w[4] = { pack2(w0.x, w0.y), pack2(w0.z, w0.w),
                                    pack2(w1.x, w1.y), pack2(w1.z, w1.w) };
        float a[8] = {a0.x, a0.y, a0.z, a0.w, a1.x, a1.y, a1.z, a1.w};
        #pragma unroll
        for (int ri = 0; ri < 8; ri++) {
            unsigned long long av = pack2(a[ri], a[ri]);
            #pragma unroll
            for (int cj = 0; cj < 4; cj++) fma2(acc[ri][cj], av, w[cj]);
        }
    }

    // W2 stage: per-row 10-wide partials, warp shuffle-reduce over tc, per-warp buffer
    #pragma unroll
    for (int ri = 0; ri < 8; ri++) {
        float p[ADIM];
        #pragma unroll
        for (int a = 0; a < ADIM; a++) p[a] = 0.f;
        #pragma unroll
        for (int cj = 0; cj < 4; cj++) {
            float2 q = unpack2(acc[ri][cj]);
            q.x = fmaxf(q.x, 0.f);
            q.y = fmaxf(q.y, 0.f);
            const float* wa = &sW2[(c0 + 2 * cj) * ADIM];
            #pragma unroll
            for (int a = 0; a < ADIM; a++)
                p[a] += q.x * wa[a] + q.y * wa[ADIM + a];
        }
        #pragma unroll
        for (int a = 0; a < ADIM; a++) {
            p[a] += __shfl_xor_sync(0xffffffffu, p[a], 8);
            p[a] += __shfl_xor_sync(0xffffffffu, p[a], 16);
        }
        if (lane < 8) {
            int row = r0 + ri;  // lane == tr here
            #pragma unroll
            for (int a = 0; a < ADIM; a++)
                sOut[wrp * 640 + row * ADIM + a] = p[a];
        }
    }
    __syncthreads();

    // reduce 8 warps' partials, add bias, write out
    for (int idx = tid; idx < 64 * ADIM; idx += 256) {
        float v = 0.f;
        #pragma unroll
        for (int w = 0; w < 8; w++) v += sOut[w * 640 + idx];
        int row = idx / ADIM, a = idx - row * ADIM;
        int node = base + row;
        if (node < N_NODES) out[(size_t)node * ADIM + a] = v + sB2[a];
    }
}

extern "C" void kernel_launch(void* const* d_in, const int* in_sizes, int n_in,
                              void* d_out, int out_size) {
    const float* x  = (const float*)d_in[0];
    const void*  ei = d_in[1];
    const float* We = (const float*)d_in[2];
    const float* be = (const float*)d_in[3];
    const float* Wg = (const float*)d_in[4];
    const float* bg = (const float*)d_in[5];
    const float* W1 = (const float*)d_in[6];
    const float* b1 = (const float*)d_in[7];
    const float* W2 = (const float*)d_in[8];
    const float* b2 = (const float*)d_in[9];
    float* out = (float*)d_out;

    const size_t smemA = (size_t)(16384 + 2 * 128 * XT_S + 128) * sizeof(float);
    const size_t smemC = (size_t)(32768 + 128 * HT_S + 2560 + 256 + 16 + 5120) * sizeof(float);
    cudaFuncSetAttribute(k_fused1, cudaFuncAttributeMaxDynamicSharedMemorySize, (int)smemA);
    cudaFuncSetAttribute(k_fused2, cudaFuncAttributeMaxDynamicSharedMemorySize, (int)smemC);

    k_detect<<<1, 32>>>((const int*)ei);
    k_init<<<2048, 256>>>();
    k_degree<<<(N_EDGES + 255) / 256, 256>>>(ei);
    k_rsqrt<<<(N_NODES + 255) / 256, 256>>>();
    k_fused1<<<(N_NODES + 127) / 128, 256, smemA>>>(x, We, be, Wg);
    k_scatter<<<(N_EDGES / 4 + 7) / 8, 256>>>(ei);
    k_fused2<<<(N_NODES + 63) / 64, 256, smemC>>>(bg, W1, b1, W2, b2, out);
}

// round 7
// speedup vs baseline: 1.2642x; 1.2642x over previous
#include <cuda_runtime.h>
#include <cstdint>

#define N_NODES 100000
#define N_EDGES 3200000
#define F 128
#define HQ 256
#define ADIM 10
#define NCHUNKS 98   // ceil(100000/1024)

// Scratch (static __device__ arrays: allocation-free per harness rules)
__device__ __align__(16) float g_xw[(size_t)N_NODES * F];   // relu(x@We+be)@Wg
__device__ __align__(16) float g_h2[(size_t)N_NODES * F];   // relu(gcn output)
__device__ float g_dinv[N_NODES];
__device__ int   g_cnt[N_NODES];
__device__ int   g_start[N_NODES + 1];
__device__ int   g_cursor[N_NODES];
__device__ int   g_src[N_EDGES];
__device__ int   g_chunksum[NCHUNKS];
__device__ int   g_chunkoff[NCHUNKS];
__device__ int   g_is64;

// ---- packed f32x2 helpers (Blackwell FFMA2 path) ----
static __device__ __forceinline__ unsigned long long pack2(float lo, float hi) {
    unsigned long long r;
    asm("mov.b64 %0, {%1, %2};" : "=l"(r) : "f"(lo), "f"(hi));
    return r;
}
static __device__ __forceinline__ void fma2(unsigned long long& d,
                                            unsigned long long a,
                                            unsigned long long b) {
    asm("fma.rn.f32x2 %0, %1, %2, %0;" : "+l"(d) : "l"(a), "l"(b));
}
static __device__ __forceinline__ float2 unpack2(unsigned long long v) {
    float2 f;
    asm("mov.b64 {%0, %1}, %2;" : "=f"(f.x), "=f"(f.y) : "l"(v));
    return f;
}

// ---- edge-index dtype detection (int64 -> all high words of first 32 vals are 0) ----
__global__ void k_detect(const int* __restrict__ ei) {
    int v = ei[2 * threadIdx.x + 1];
    unsigned m = __ballot_sync(0xffffffffu, v != 0);
    if (threadIdx.x == 0) g_is64 = (m == 0) ? 1 : 0;
}

static __device__ __forceinline__ int eidx(const void* ei, int is64, long long pos) {
    return is64 ? (int)((const long long*)ei)[pos] : ((const int*)ei)[pos];
}

// ---- zero histogram counters ----
__global__ void k_zero() {
    int i = blockIdx.x * blockDim.x + threadIdx.x;
    if (i < N_NODES) g_cnt[i] = 0;
}

// ---- histogram of dst (doubles as in-degree count) ----
__global__ void k_hist(const void* __restrict__ ei) {
    int is64 = g_is64;
    int e = blockIdx.x * blockDim.x + threadIdx.x;
    if (e < N_EDGES) atomicAdd(&g_cnt[eidx(ei, is64, (long long)N_EDGES + e)], 1);
}

// ---- scan stage A: per-1024-chunk sums; also dinv = rsqrt(cnt+1) ----
__global__ void k_scanA() {
    __shared__ int wsum[8];
    int t = threadIdx.x;
    int base = blockIdx.x * 1024 + t * 4;
    int s = 0;
    #pragma unroll
    for (int i = 0; i < 4; i++) {
        int idx = base + i;
        if (idx < N_NODES) {
            int c = g_cnt[idx];
            s += c;
            g_dinv[idx] = rsqrtf((float)(c + 1));
        }
    }
    #pragma unroll
    for (int o = 16; o > 0; o >>= 1) s += __shfl_down_sync(0xffffffffu, s, o);
    if ((t & 31) == 0) wsum[t >> 5] = s;
    __syncthreads();
    if (t == 0) {
        int tot = 0;
        #pragma unroll
        for (int w = 0; w < 8; w++) tot += wsum[w];
        g_chunksum[blockIdx.x] = tot;
    }
}

// ---- scan stage B: exclusive scan of chunk sums ----
__global__ void k_scanB() {
    __shared__ int sv[NCHUNKS];
    int t = threadIdx.x;
    if (t < NCHUNKS) sv[t] = g_chunksum[t];
    __syncthreads();
    if (t == 0) {
        int acc = 0;
        for (int b = 0; b < NCHUNKS; b++) { int x = sv[b]; sv[b] = acc; acc += x; }
        g_start[N_NODES] = acc;
    }
    __syncthreads();
    if (t < NCHUNKS) g_chunkoff[t] = sv[t];
}

// ---- scan stage C: within-chunk exclusive scan -> start, cursor ----
__global__ void k_scanC() {
    __shared__ int wsum[8];
    int t = threadIdx.x;
    int lane = t & 31, wid = t >> 5;
    int base = blockIdx.x * 1024 + t * 4;
    int v[4];
    int s = 0;
    #pragma unroll
    for (int i = 0; i < 4; i++) {
        int idx = base + i;
        v[i] = (idx < N_NODES) ? g_cnt[idx] : 0;
        s += v[i];
    }
    int inc = s;
    #pragma unroll
    for (int o = 1; o < 32; o <<= 1) {
        int n = __shfl_up_sync(0xffffffffu, inc, o);
        if (lane >= o) inc += n;
    }
    if (lane == 31) wsum[wid] = inc;
    __syncthreads();
    if (t == 0) {
        int acc = 0;
        #pragma unroll
        for (int w = 0; w < 8; w++) { int x = wsum[w]; wsum[w] = acc; acc += x; }
    }
    __syncthreads();
    int excl = inc - s + wsum[wid] + g_chunkoff[blockIdx.x];
    #pragma unroll
    for (int i = 0; i < 4; i++) {
        int idx = base + i;
        if (idx < N_NODES) { g_start[idx] = excl; g_cursor[idx] = excl; }
        excl += v[i];
    }
}

// ---- permute edges into dst-grouped order ----
__global__ void k_permute(const void* __restrict__ ei) {
    int is64 = g_is64;
    int e = blockIdx.x * blockDim.x + threadIdx.x;
    if (e < N_EDGES) {
        int s = eidx(ei, is64, e);
        int d = eidx(ei, is64, (long long)N_EDGES + e);
        int pos = atomicAdd(&g_cursor[d], 1);
        g_src[pos] = s;
    }
}

// ==================== fused1: xw = relu(x@We + be) @ Wg ====================
#define XT_S 132

__global__ void __launch_bounds__(256, 1)
k_fused1(const float* __restrict__ x, const float* __restrict__ We,
         const float* __restrict__ be, const float* __restrict__ Wg) {
    extern __shared__ float smem[];
    float* sW  = smem;                    // 128*128
    float* sXT = smem + 16384;            // 128 * XT_S
    float* sHT = sXT + 128 * XT_S;        // 128 * XT_S
    float* sBe = sHT + 128 * XT_S;        // 128

    const int tid = threadIdx.x;
    const int base = blockIdx.x * 128;

    for (int idx = tid; idx < 16384; idx += 256) sW[idx] = We[idx];
    if (tid < 128) sBe[tid] = be[tid];
    for (int idx = tid; idx < 128 * F; idx += 256) {
        int r = idx >> 7, c = idx & 127;
        int node = base + r;
        sXT[c * XT_S + r] = (node < N_NODES) ? x[(size_t)node * F + c] : 0.f;
    }
    __syncthreads();

    const int tr = tid & 15, tc = tid >> 4;
    const int r0 = tr * 8, c0 = tc * 8;

    unsigned long long acc[8][4];
    #pragma unroll
    for (int ri = 0; ri < 8; ri++)
        #pragma unroll
        for (int cj = 0; cj < 4; cj++)
            acc[ri][cj] = pack2(sBe[c0 + 2 * cj], sBe[c0 + 2 * cj + 1]);

    #pragma unroll 4
    for (int k = 0; k < F; k++) {
        float4 a0 = *(const float4*)&sXT[k * XT_S + r0];
        float4 a1 = *(const float4*)&sXT[k * XT_S + r0 + 4];
        float4 w0 = *(const float4*)&sW[k * F + c0];
        float4 w1 = *(const float4*)&sW[k * F + c0 + 4];
        unsigned long long w[4] = { pack2(w0.x, w0.y), pack2(w0.z, w0.w),
                                    pack2(w1.x, w1.y), pack2(w1.z, w1.w) };
        float a[8] = {a0.x, a0.y, a0.z, a0.w, a1.x, a1.y, a1.z, a1.w};
        #pragma unroll
        for (int ri = 0; ri < 8; ri++) {
            unsigned long long av = pack2(a[ri], a[ri]);
            #pragma unroll
            for (int cj = 0; cj < 4; cj++) fma2(acc[ri][cj], av, w[cj]);
        }
    }

    #pragma unroll
    for (int cj = 0; cj < 4; cj++) {
        float2 v[8];
        #pragma unroll
        for (int ri = 0; ri < 8; ri++) v[ri] = unpack2(acc[ri][cj]);
        int c = c0 + 2 * cj;
        *(float4*)&sHT[c * XT_S + r0] =
            make_float4(fmaxf(v[0].x, 0.f), fmaxf(v[1].x, 0.f),
                        fmaxf(v[2].x, 0.f), fmaxf(v[3].x, 0.f));
        *(float4*)&sHT[c * XT_S + r0 + 4] =
            make_float4(fmaxf(v[4].x, 0.f), fmaxf(v[5].x, 0.f),
                        fmaxf(v[6].x, 0.f), fmaxf(v[7].x, 0.f));
        *(float4*)&sHT[(c + 1) * XT_S + r0] =
            make_float4(fmaxf(v[0].y, 0.f), fmaxf(v[1].y, 0.f),
                        fmaxf(v[2].y, 0.f), fmaxf(v[3].y, 0.f));
        *(float4*)&sHT[(c + 1) * XT_S + r0 + 4] =
            make_float4(fmaxf(v[4].y, 0.f), fmaxf(v[5].y, 0.f),
                        fmaxf(v[6].y, 0.f), fmaxf(v[7].y, 0.f));
    }
    __syncthreads();
    for (int idx = tid; idx < 16384; idx += 256) sW[idx] = Wg[idx];
    __syncthreads();

    #pragma unroll
    for (int ri = 0; ri < 8; ri++)
        #pragma unroll
        for (int cj = 0; cj < 4; cj++) acc[ri][cj] = 0ULL;

    #pragma unroll 4
    for (int k = 0; k < F; k++) {
        float4 a0 = *(const float4*)&sHT[k * XT_S + r0];
        float4 a1 = *(const float4*)&sHT[k * XT_S + r0 + 4];
        float4 w0 = *(const float4*)&sW[k * F + c0];
        float4 w1 = *(const float4*)&sW[k * F + c0 + 4];
        unsigned long long w[4] = { pack2(w0.x, w0.y), pack2(w0.z, w0.w),
                                    pack2(w1.x, w1.y), pack2(w1.z, w1.w) };
        float a[8] = {a0.x, a0.y, a0.z, a0.w, a1.x, a1.y, a1.z, a1.w};
        #pragma unroll
        for (int ri = 0; ri < 8; ri++) {
            unsigned long long av = pack2(a[ri], a[ri]);
            #pragma unroll
            for (int cj = 0; cj < 4; cj++) fma2(acc[ri][cj], av, w[cj]);
        }
    }

    #pragma unroll
    for (int ri = 0; ri < 8; ri++) {
        int node = base + r0 + ri;
        if (node < N_NODES) {
            float* dst = &g_xw[(size_t)node * F + c0];
            *(ulonglong2*)(dst)     = make_ulonglong2(acc[ri][0], acc[ri][1]);
            *(ulonglong2*)(dst + 4) = make_ulonglong2(acc[ri][2], acc[ri][3]);
        }
    }
}

// ==================== aggregate: warp-per-node segment sum ====================
// h2[d] = relu( dinv[d] * sum_j dinv[src_j]*xw[src_j] + dinv[d]^2 * xw[d] + bg )
__global__ void __launch_bounds__(256)
k_aggregate(const float* __restrict__ bg) {
    int warp = (blockIdx.x * blockDim.x + threadIdx.x) >> 5;
    int lane = threadIdx.x & 31;
    if (warp >= N_NODES) return;

    const float4* xw4 = reinterpret_cast<const float4*>(g_xw);
    int j0 = g_start[warp], j1 = g_start[warp + 1];

    float4 a0 = make_float4(0.f, 0.f, 0.f, 0.f);
    float4 a1 = a0, a2 = a0, a3 = a0;

    int j = j0;
    for (; j + 4 <= j1; j += 4) {
        int s0 = g_src[j], s1 = g_src[j + 1], s2 = g_src[j + 2], s3 = g_src[j + 3];
        float c0 = g_dinv[s0], c1 = g_dinv[s1], c2 = g_dinv[s2], c3 = g_dinv[s3];
        float4 v0 = xw4[(size_t)s0 * 32 + lane];
        float4 v1 = xw4[(size_t)s1 * 32 + lane];
        float4 v2 = xw4[(size_t)s2 * 32 + lane];
        float4 v3 = xw4[(size_t)s3 * 32 + lane];
        a0.x += v0.x * c0; a0.y += v0.y * c0; a0.z += v0.z * c0; a0.w += v0.w * c0;
        a1.x += v1.x * c1; a1.y += v1.y * c1; a1.z += v1.z * c1; a1.w += v1.w * c1;
        a2.x += v2.x * c2; a2.y += v2.y * c2; a2.z += v2.z * c2; a2.w += v2.w * c2;
        a3.x += v3.x * c3; a3.y += v3.y * c3; a3.z += v3.z * c3; a3.w += v3.w * c3;
    }
    for (; j < j1; j++) {
        int s = g_src[j];
        float c = g_dinv[s];
        float4 v = xw4[(size_t)s * 32 + lane];
        a0.x += v.x * c; a0.y += v.y * c; a0.z += v.z * c; a0.w += v.w * c;
    }
    float4 acc = make_float4(a0.x + a1.x + a2.x + a3.x,
                             a0.y + a1.y + a2.y + a3.y,
                             a0.z + a1.z + a2.z + a3.z,
                             a0.w + a1.w + a2.w + a3.w);

    float dd = g_dinv[warp];
    float dd2 = dd * dd;
    float4 self = xw4[(size_t)warp * 32 + lane];
    float4 bgv = *reinterpret_cast<const float4*>(&bg[lane * 4]);
    float4 h;
    h.x = fmaxf(dd * acc.x + dd2 * self.x + bgv.x, 0.f);
    h.y = fmaxf(dd * acc.y + dd2 * self.y + bgv.y, 0.f);
    h.z = fmaxf(dd * acc.z + dd2 * self.z + bgv.z, 0.f);
    h.w = fmaxf(dd * acc.w + dd2 * self.w + bgv.w, 0.f);
    reinterpret_cast<float4*>(g_h2)[(size_t)warp * 32 + lane] = h;
}

// ==================== fused2: out = relu(h2@W1+b1)@W2+b2 ====================
#define HT_S 68

__global__ void __launch_bounds__(256, 1)
k_fused2(const float* __restrict__ W1, const float* __restrict__ b1,
         const float* __restrict__ W2, const float* __restrict__ b2,
         float* __restrict__ out) {
    extern __shared__ float smem[];
    float* sW1  = smem;                   // 32768
    float* sHT  = sW1 + 32768;            // 128 * HT_S
    float* sW2  = sHT + 128 * HT_S;       // 2560
    float* sB1  = sW2 + 2560;             // 256
    float* sB2  = sB1 + 256;              // 16
    float* sOut = sB2 + 16;               // 8 * 640

    const int tid = threadIdx.x;
    const int base = blockIdx.x * 64;

    for (int idx = tid; idx < 32768; idx += 256) sW1[idx] = W1[idx];
    for (int idx = tid; idx < 2560; idx += 256) sW2[idx] = W2[idx];
    sB1[tid] = b1[tid];
    if (tid < ADIM) sB2[tid] = b2[tid];

    for (int idx = tid; idx < 64 * F; idx += 256) {
        int r = idx >> 7, c = idx & 127;
        int node = base + r;
        sHT[c * HT_S + r] = (node < N_NODES) ? g_h2[(size_t)node * F + c] : 0.f;
    }
    __syncthreads();

    const int tr = tid & 7, tc = tid >> 3;
    const int r0 = tr * 8, c0 = tc * 8;
    const int lane = tid & 31, wrp = tid >> 5;

    unsigned long long acc[8][4];
    #pragma unroll
    for (int ri = 0; ri < 8; ri++)
        #pragma unroll
        for (int cj = 0; cj < 4; cj++)
            acc[ri][cj] = pack2(sB1[c0 + 2 * cj], sB1[c0 + 2 * cj + 1]);

    #pragma unroll 4
    for (int k = 0; k < F; k++) {
        float4 a0 = *(const float4*)&sHT[k * HT_S + r0];
        float4 a1 = *(const float4*)&sHT[k * HT_S + r0 + 4];
        float4 w0 = *(const float4*)&sW1[k * HQ + c0];
        float4 w1 = *(const float4*)&sW1[k * HQ + c0 + 4];
        unsigned long long w[4] = { pack2(w0.x, w0.y), pack2(w0.z, w0.w),
                                    pack2(w1.x, w1.y), pack2(w1.z, w1.w) };
        float a[8] = {a0.x, a0.y, a0.z, a0.w, a1.x, a1.y, a1.z, a1.w};
        #pragma unroll
        for (int ri = 0; ri < 8; ri++) {
            unsigned long long av = pack2(a[ri], a[ri]);
            #pragma unroll
            for (int cj = 0; cj < 4; cj++) fma2(acc[ri][cj], av, w[cj]);
        }
    }

    #pragma unroll
    for (int ri = 0; ri < 8; ri++) {
        float p[ADIM];
        #pragma unroll
        for (int a = 0; a < ADIM; a++) p[a] = 0.f;
        #pragma unroll
        for (int cj = 0; cj < 4; cj++) {
            float2 q = unpack2(acc[ri][cj]);
            q.x = fmaxf(q.x, 0.f);
            q.y = fmaxf(q.y, 0.f);
            const float* wa = &sW2[(c0 + 2 * cj) * ADIM];
            #pragma unroll
            for (int a = 0; a < ADIM; a++)
                p[a] += q.x * wa[a] + q.y * wa[ADIM + a];
        }
        #pragma unroll
        for (int a = 0; a < ADIM; a++) {
            p[a] += __shfl_xor_sync(0xffffffffu, p[a], 8);
            p[a] += __shfl_xor_sync(0xffffffffu, p[a], 16);
        }
        if (lane < 8) {
            int row = r0 + ri;
            #pragma unroll
            for (int a = 0; a < ADIM; a++)
                sOut[wrp * 640 + row * ADIM + a] = p[a];
        }
    }
    __syncthreads();

    for (int idx = tid; idx < 64 * ADIM; idx += 256) {
        float v = 0.f;
        #pragma unroll
        for (int w = 0; w < 8; w++) v += sOut[w * 640 + idx];
        int row = idx / ADIM, a = idx - row * ADIM;
        int node = base + row;
        if (node < N_NODES) out[(size_t)node * ADIM + a] = v + sB2[a];
    }
}

extern "C" void kernel_launch(void* const* d_in, const int* in_sizes, int n_in,
                              void* d_out, int out_size) {
    const float* x  = (const float*)d_in[0];
    const void*  ei = d_in[1];
    const float* We = (const float*)d_in[2];
    const float* be = (const float*)d_in[3];
    const float* Wg = (const float*)d_in[4];
    const float* bg = (const float*)d_in[5];
    const float* W1 = (const float*)d_in[6];
    const float* b1 = (const float*)d_in[7];
    const float* W2 = (const float*)d_in[8];
    const float* b2 = (const float*)d_in[9];
    float* out = (float*)d_out;

    const size_t smemA = (size_t)(16384 + 2 * 128 * XT_S + 128) * sizeof(float);
    const size_t smemC = (size_t)(32768 + 128 * HT_S + 2560 + 256 + 16 + 5120) * sizeof(float);
    cudaFuncSetAttribute(k_fused1, cudaFuncAttributeMaxDynamicSharedMemorySize, (int)smemA);
    cudaFuncSetAttribute(k_fused2, cudaFuncAttributeMaxDynamicSharedMemorySize, (int)smemC);

    k_zero<<<(N_NODES + 1023) / 1024, 1024>>>();
    k_detect<<<1, 32>>>((const int*)ei);
    k_hist<<<(N_EDGES + 255) / 256, 256>>>(ei);
    k_scanA<<<NCHUNKS, 256>>>();
    k_scanB<<<1, 128>>>();
    k_scanC<<<NCHUNKS, 256>>>();
    k_permute<<<(N_EDGES + 255) / 256, 256>>>(ei);
    k_fused1<<<(N_NODES + 127) / 128, 256, smemA>>>(x, We, be, Wg);
    k_aggregate<<<(N_NODES * 32 + 255) / 256, 256>>>(bg);
    k_fused2<<<(N_NODES + 63) / 64, 256, smemC>>>(W1, b1, W2, b2, out);
}